// round 16
// baseline (speedup 1.0000x reference)
#include <cuda_runtime.h>
#include <cuda_fp16.h>
#include <math.h>
#include <stdint.h>

// Problem dims
#define Tn 1024
#define Sn 1024
#define Bn 4
#define En 1024
#define Hn 16
#define DHn 64
#define FFn 4096
#define ROWS (Tn*Bn)
#define BH (Bn*Hn)
#define MEG (1024*1024)

// -------- scratch (device globals; no allocation) --------
__device__ float g_xq[ROWS*En];        // used as __half
__device__ float g_xk[ROWS*En];        // used as __half
__device__ float g_xv[ROWS*En];        // used as __half
__device__ float g_attn[ROWS*En];      // used as __half
__device__ float g_tmp[ROWS*En];
__device__ float g_state1[ROWS*En];
__device__ float g_state2[ROWS*En];
__device__ float g_st1r[ROWS*En];      // used as __half
__device__ float g_st2r[ROWS*En];      // used as __half
__device__ float g_ffn[ROWS*FFn];      // used as __half
__device__ float2 g_stats[BH*Tn];
__device__ float g_rw[24*MEG];         // used as __half pool (48M halfs)

// ======================= helpers =======================
__device__ __forceinline__ void mma_f16(float* c, const uint32_t* a, const uint32_t* b) {
    asm volatile(
        "mma.sync.aligned.m16n8k16.row.col.f32.f16.f16.f32 "
        "{%0,%1,%2,%3}, {%4,%5,%6,%7}, {%8,%9}, {%0,%1,%2,%3};"
        : "+f"(c[0]), "+f"(c[1]), "+f"(c[2]), "+f"(c[3])
        : "r"(a[0]), "r"(a[1]), "r"(a[2]), "r"(a[3]), "r"(b[0]), "r"(b[1]));
}
__device__ __forceinline__ void ldsm4(uint32_t* r, uint32_t addr) {
    asm volatile("ldmatrix.sync.aligned.m8n8.x4.shared.b16 {%0,%1,%2,%3}, [%4];"
        : "=r"(r[0]), "=r"(r[1]), "=r"(r[2]), "=r"(r[3]) : "r"(addr));
}
__device__ __forceinline__ void ldsm4t(uint32_t* r, uint32_t addr) {
    asm volatile("ldmatrix.sync.aligned.m8n8.x4.trans.shared.b16 {%0,%1,%2,%3}, [%4];"
        : "=r"(r[0]), "=r"(r[1]), "=r"(r[2]), "=r"(r[3]) : "r"(addr));
}
__device__ __forceinline__ void cp16(uint32_t dst, const void* src) {
    asm volatile("cp.async.cg.shared.global [%0], [%1], 16;" :: "r"(dst), "l"(src));
}
__device__ __forceinline__ void cp_commit() {
    asm volatile("cp.async.commit_group;" ::: "memory");
}
__device__ __forceinline__ void cp_wait0() {
    asm volatile("cp.async.wait_group 0;" ::: "memory");
}
__device__ __forceinline__ void cp_wait1() {
    asm volatile("cp.async.wait_group 1;" ::: "memory");
}
__device__ __forceinline__ uint32_t smaddr(const void* p) {
    return (uint32_t)__cvta_generic_to_shared(p);
}
__device__ __forceinline__ uint32_t hex2(uint32_t x) {
    uint32_t r;
    asm("ex2.approx.f16x2 %0, %1;" : "=r"(r) : "r"(x));
    return r;
}
__device__ __forceinline__ uint32_t packh2(float a, float b) {
    __half2 h = __floats2half2_rn(a, b);
    return *(uint32_t*)&h;
}

// ======================= hgemm2: 128x256 tile, 512 thr, 4x4 warps ============
// C[m,n] = sum_k A[m,k]*B[n,k] + bias[n]; A:[M,K] half; B:[N,K] half.
// Warp tile 32x64 (MI=2, NI=8). K-slab 64 halfs, 3 cp.async stages.
// postop (per job): 0 fp32 out; 1 relu->half; 2 half; 3 (v*0.125)->half.
struct JobH { const __half* A; const __half* B; const float* bias; void* C; int postop; };
struct JobsH { JobH j[3]; };

#define H2_WS 36
#define H2_ATILEW (128*H2_WS)            // 4608 words
#define H2_STAGEW (384*H2_WS)            // A(128)+B(256) rows = 13824 words
#define H2_SMEM (3*H2_STAGEW*4)          // 165888 bytes

__global__ __launch_bounds__(512, 1) void hgemm2(
    JobsH jobs, int K, int N)
{
    extern __shared__ uint32_t smw[];
    const int tid  = threadIdx.x;
    const int lane = tid & 31;
    const int wid  = tid >> 5;
    const int wm = wid & 3, wn = wid >> 2;       // 4 x 4 warp grid
    const int m_base = wm * 32, n_base = wn * 64;
    const int g  = lane >> 2;
    const int tg = lane & 3;

    const JobH job = jobs.j[blockIdx.z];
    const int postop = job.postop;
    const int bm = blockIdx.y * 128;
    const int bn = blockIdx.x * 256;
    const __half* A = job.A + (long)bm * K;
    const __half* B = job.B + (long)bn * K;

    const int r0 = tid >> 3, c8 = tid & 7;       // rows 0..63, 8 chunks/row
    const __half* aPtr = A + (long)r0 * K + c8 * 8;
    const __half* bPtr = B + (long)r0 * K + c8 * 8;
    const uint32_t aSm = smaddr(smw + r0 * H2_WS + c8 * 4);
    const uint32_t bSm = smaddr(smw + H2_ATILEW + r0 * H2_WS + c8 * 4);
    const long rowAdv = 64L * K;

    auto load_slab = [&](int s, int st) {
        const uint32_t so = st * (H2_STAGEW * 4);
        const __half* ap = aPtr + s * 64;
        const __half* bp = bPtr + s * 64;
        #pragma unroll
        for (int it = 0; it < 2; it++)
            cp16(aSm + so + it * (64 * H2_WS * 4), ap + it * rowAdv);
        #pragma unroll
        for (int it = 0; it < 4; it++)
            cp16(bSm + so + it * (64 * H2_WS * 4), bp + it * rowAdv);
        cp_commit();
    };

    uint32_t aLd[2];
    {
        int rowl = lane & 15;
        uint32_t kcb = (lane >> 4) * 16;
        #pragma unroll
        for (int mi = 0; mi < 2; mi++)
            aLd[mi] = smaddr(smw + (m_base + mi * 16 + rowl) * H2_WS) + kcb;
    }
    uint32_t bLd[4];
    {
        int rowl = (lane & 7) + ((lane >> 4) * 8);
        uint32_t kcb = ((lane >> 3) & 1) * 16;
        #pragma unroll
        for (int p = 0; p < 4; p++)
            bLd[p] = smaddr(smw + H2_ATILEW + (n_base + p * 16 + rowl) * H2_WS) + kcb;
    }

    float acc[2][8][4];
    #pragma unroll
    for (int mi = 0; mi < 2; mi++)
        #pragma unroll
        for (int ni = 0; ni < 8; ni++)
            #pragma unroll
            for (int r = 0; r < 4; r++) acc[mi][ni][r] = 0.f;

    const int nslab = K >> 6;
    load_slab(0, 0);
    if (nslab > 1) load_slab(1, 1); else cp_commit();

    int st = 0;
    for (int s = 0; s < nslab; s++) {
        cp_wait1();
        __syncthreads();
        if (s + 2 < nslab) load_slab(s + 2, (st + 2) % 3);
        else cp_commit();

        const uint32_t so = st * (H2_STAGEW * 4);

        #pragma unroll
        for (int kw = 0; kw < 32; kw += 8) {
            uint32_t afr[2][4], bfr[4][4];
            #pragma unroll
            for (int mi = 0; mi < 2; mi++) ldsm4(afr[mi], aLd[mi] + so + kw * 4);
            #pragma unroll
            for (int p = 0; p < 4; p++)    ldsm4(bfr[p], bLd[p] + so + kw * 4);
            #pragma unroll
            for (int mi = 0; mi < 2; mi++)
                #pragma unroll
                for (int ni = 0; ni < 8; ni++) {
                    uint32_t bq[2] = { bfr[ni >> 1][(ni & 1) * 2],
                                       bfr[ni >> 1][(ni & 1) * 2 + 1] };
                    mma_f16(acc[mi][ni], afr[mi], bq);
                }
        }
        st = (st + 1) % 3;
    }

    const float* bias = job.bias;
    #pragma unroll
    for (int mi = 0; mi < 2; mi++) {
        int row0 = bm + m_base + mi * 16 + g;
        #pragma unroll
        for (int ni = 0; ni < 8; ni++) {
            int col = bn + n_base + ni * 8 + tg * 2;
            float b0 = bias[col], b1 = bias[col + 1];
            float v0 = acc[mi][ni][0] + b0;
            float v1 = acc[mi][ni][1] + b1;
            float v2 = acc[mi][ni][2] + b0;
            float v3 = acc[mi][ni][3] + b1;
            if (postop == 0) {
                float* C = (float*)job.C;
                *(float2*)&C[(long)row0 * N + col]       = make_float2(v0, v1);
                *(float2*)&C[(long)(row0 + 8) * N + col] = make_float2(v2, v3);
            } else {
                if (postop == 1) {
                    v0 = fmaxf(v0, 0.f); v1 = fmaxf(v1, 0.f);
                    v2 = fmaxf(v2, 0.f); v3 = fmaxf(v3, 0.f);
                } else if (postop == 3) {
                    v0 *= 0.125f; v1 *= 0.125f; v2 *= 0.125f; v3 *= 0.125f;
                }
                __half* C = (__half*)job.C;
                *(__half2*)&C[(long)row0 * N + col]       = __floats2half2_rn(v0, v1);
                *(__half2*)&C[(long)(row0 + 8) * N + col] = __floats2half2_rn(v2, v3);
            }
        }
    }
}

// ======================= fp16 fused flash attention =======================
// Q pre-scaled by 1/8. exp via ex2.approx.f16x2; row sums via ones-column MMA.
#define FLH_SMEM (18432*4)
#define LOG2E 1.4426950408889634f

template<bool CAUSAL>
__global__ __launch_bounds__(256, 2) void flash_h(
    const __half* __restrict__ Qp, const __half* __restrict__ Kp,
    const __half* __restrict__ Vp, __half* __restrict__ Op,
    float2* __restrict__ stats)
{
    extern __shared__ uint32_t smw[];
    const int tid = threadIdx.x;
    const int lane = tid & 31, w = tid >> 5;
    const int g = lane >> 2, tg = lane & 3;
    const int bh = blockIdx.y;
    const int it = CAUSAL ? ((int)gridDim.x - 1 - (int)blockIdx.x) : (int)blockIdx.x;
    const int t0 = it * 128;
    const int nIter = CAUSAL ? 2 * it + 2 : 16;

    const __half* Qg = Qp + (long)t0 * 4096 + bh * 64;
    const __half* Kg = Kp + bh * 64;
    const __half* Vg = Vp + bh * 64;

    auto loadKV = [&](int j, int buf) {
        const long s0 = (long)j * 64;
        const uint32_t kb = smaddr(smw + 4608 + buf * 2304);
        const uint32_t vb = smaddr(smw + 9216 + buf * 2304);
        #pragma unroll
        for (int i = 0; i < 2; i++) {
            int idx = tid + i * 256;
            int row = idx >> 3, c = idx & 7;
            cp16(kb + row * 144 + c * 16, Kg + (s0 + row) * 4096 + c * 8);
            cp16(vb + row * 144 + c * 16, Vg + (s0 + row) * 4096 + c * 8);
        }
    };

    #pragma unroll
    for (int i = 0; i < 4; i++) {
        int idx = tid + i * 256;
        int row = idx >> 3, c = idx & 7;
        cp16(smaddr(smw) + row * 144 + c * 16, Qg + (long)row * 4096 + c * 8);
    }
    loadKV(0, 0);
    cp_commit();
    cp_wait0();
    __syncthreads();

    uint32_t qf[4][4];
    {
        uint32_t qbase = smaddr(smw) + (16 * w + (lane & 15)) * 144 + (lane >> 4) * 16;
        #pragma unroll
        for (int kk = 0; kk < 4; kk++) ldsm4(qf[kk], qbase + kk * 32);
    }
    uint32_t kbl[4];
    {
        int rowl = (lane & 7) + ((lane >> 4) * 8);
        uint32_t kcb = ((lane >> 3) & 1) * 16;
        #pragma unroll
        for (int p = 0; p < 4; p++)
            kbl[p] = smaddr(smw + 4608) + (p * 16 + rowl) * 144 + kcb;
    }
    uint32_t vbl[4];
    {
        int rowv = (lane & 7) + (((lane >> 3) & 1) * 8);
        uint32_t kcv = (lane >> 4) * 16;
        #pragma unroll
        for (int p = 0; p < 4; p++)
            vbl[p] = smaddr(smw + 9216) + rowv * 144 + kcv + p * 32;
    }
    uint32_t pbase = smaddr(smw + 13824) + (16 * w + (lane & 15)) * 144 + (lane >> 4) * 16;
    __half* Pw = (__half*)(smw + 13824) + (16 * w + g) * 72;

    float acc_o[8][4];
    #pragma unroll
    for (int ni = 0; ni < 8; ni++)
        #pragma unroll
        for (int r = 0; r < 4; r++) acc_o[ni][r] = 0.f;
    float acc_l[4] = {0.f, 0.f, 0.f, 0.f};
    float m0 = -1e30f, m1 = -1e30f;

    const uint32_t ONE2 = 0x3C003C00u;
    uint32_t ones_bq[2] = {ONE2, ONE2};

    for (int j = 0; j < nIter; j++) {
        const int buf = j & 1;
        const uint32_t bofs = buf * 9216;
        if (j + 1 < nIter) { loadKV(j + 1, buf ^ 1); cp_commit(); }

        float s_acc[8][4];
        #pragma unroll
        for (int ni = 0; ni < 8; ni++)
            #pragma unroll
            for (int r = 0; r < 4; r++) s_acc[ni][r] = 0.f;
        #pragma unroll
        for (int kk = 0; kk < 4; kk++) {
            uint32_t kfr[4][4];
            #pragma unroll
            for (int p = 0; p < 4; p++) ldsm4(kfr[p], kbl[p] + bofs + kk * 32);
            #pragma unroll
            for (int ni = 0; ni < 8; ni++) {
                uint32_t bq[2] = { kfr[ni >> 1][(ni & 1) * 2],
                                   kfr[ni >> 1][(ni & 1) * 2 + 1] };
                mma_f16(s_acc[ni], qf[kk], bq);
            }
        }

        const int s0 = j * 64;
        const bool need = CAUSAL && (s0 + 63 > t0 + 16 * w);
        const int tr0 = t0 + 16 * w + g, tr1 = tr0 + 8;
        float mx0 = -1e30f, mx1 = -1e30f;
        #pragma unroll
        for (int ni = 0; ni < 8; ni++) {
            float v0 = s_acc[ni][0];
            float v1 = s_acc[ni][1];
            float v2 = s_acc[ni][2];
            float v3 = s_acc[ni][3];
            if (need) {
                int c0 = s0 + ni * 8 + 2 * tg, c1 = c0 + 1;
                if (c0 > tr0) v0 -= 1e9f;
                if (c1 > tr0) v1 -= 1e9f;
                if (c0 > tr1) v2 -= 1e9f;
                if (c1 > tr1) v3 -= 1e9f;
                s_acc[ni][0] = v0; s_acc[ni][1] = v1;
                s_acc[ni][2] = v2; s_acc[ni][3] = v3;
            }
            mx0 = fmaxf(mx0, fmaxf(v0, v1));
            mx1 = fmaxf(mx1, fmaxf(v2, v3));
        }
        mx0 = fmaxf(mx0, __shfl_xor_sync(0xffffffffu, mx0, 1));
        mx0 = fmaxf(mx0, __shfl_xor_sync(0xffffffffu, mx0, 2));
        mx1 = fmaxf(mx1, __shfl_xor_sync(0xffffffffu, mx1, 1));
        mx1 = fmaxf(mx1, __shfl_xor_sync(0xffffffffu, mx1, 2));
        const float mn0 = fmaxf(m0, mx0), mn1 = fmaxf(m1, mx1);
        const float sc0 = __expf(m0 - mn0), sc1 = __expf(m1 - mn1);
        m0 = mn0; m1 = mn1;
        const float nm0 = m0 * LOG2E, nm1 = m1 * LOG2E;

        #pragma unroll
        for (int ni = 0; ni < 8; ni++) {
            float t0v = fmaf(s_acc[ni][0], LOG2E, -nm0);
            float t1v = fmaf(s_acc[ni][1], LOG2E, -nm0);
            float t2v = fmaf(s_acc[ni][2], LOG2E, -nm1);
            float t3v = fmaf(s_acc[ni][3], LOG2E, -nm1);
            *(uint32_t*)&Pw[ni * 8 + 2 * tg]          = hex2(packh2(t0v, t1v));
            *(uint32_t*)&Pw[8 * 72 + ni * 8 + 2 * tg] = hex2(packh2(t2v, t3v));
        }
        #pragma unroll
        for (int ni = 0; ni < 8; ni++) {
            acc_o[ni][0] *= sc0; acc_o[ni][1] *= sc0;
            acc_o[ni][2] *= sc1; acc_o[ni][3] *= sc1;
        }
        acc_l[0] *= sc0; acc_l[1] *= sc0;
        acc_l[2] *= sc1; acc_l[3] *= sc1;
        __syncwarp();

        #pragma unroll
        for (int kk = 0; kk < 4; kk++) {
            uint32_t pf[4];
            ldsm4(pf, pbase + kk * 32);
            mma_f16(acc_l, pf, ones_bq);
            uint32_t vfr[4][4];
            #pragma unroll
            for (int p = 0; p < 4; p++) ldsm4t(vfr[p], vbl[p] + bofs + kk * 2304);
            #pragma unroll
            for (int ni = 0; ni < 8; ni++) {
                uint32_t bq[2] = { vfr[ni >> 1][(ni & 1) * 2],
                                   vfr[ni >> 1][(ni & 1) * 2 + 1] };
                mma_f16(acc_o[ni], pf, bq);
            }
        }
        if (j + 1 < nIter) cp_wait0();
        __syncthreads();
    }

    const float l0 = acc_l[0], l1 = acc_l[2];
    const float inv0 = 1.f / l0, inv1 = 1.f / l1;
    const int r0 = t0 + 16 * w + g;
    __half* o0 = Op + (long)r0 * 4096 + bh * 64;
    __half* o1 = o0 + 8L * 4096;
    #pragma unroll
    for (int ni = 0; ni < 8; ni++) {
        *(__half2*)&o0[ni * 8 + 2 * tg] =
            __floats2half2_rn(acc_o[ni][0] * inv0, acc_o[ni][1] * inv0);
        *(__half2*)&o1[ni * 8 + 2 * tg] =
            __floats2half2_rn(acc_o[ni][2] * inv1, acc_o[ni][3] * inv1);
    }
    if (!CAUSAL && tg == 0) {
        stats[bh * Tn + r0]     = make_float2(m0, l0);
        stats[bh * Tn + r0 + 8] = make_float2(m1, l1);
    }
}

// ======================= wgemm: EA normalized attention weights ============
#define WG_SMEM (9216*4)

__global__ __launch_bounds__(256, 2) void wgemm(
    const __half* __restrict__ Qh, const __half* __restrict__ Kh,
    const float2* __restrict__ stats, float* __restrict__ C)
{
    extern __shared__ uint32_t smw[];
    const int tid  = threadIdx.x;
    const int lane = tid & 31;
    const int wid  = tid >> 5;
    const int wm = wid & 1, wn = wid >> 1;
    const int m_base = wm * 64, n_base = wn * 32;
    const int g  = lane >> 2;
    const int tg = lane & 3;
    const int z  = blockIdx.z;
    const int bm = blockIdx.y * 128;
    const int bn = blockIdx.x * 128;

    const __half* A = Qh + (long)z * 64 + (long)bm * 4096;
    const __half* B = Kh + (long)z * 64 + (long)bn * 4096;

    #pragma unroll
    for (int i = 0; i < 4; i++) {
        int idx = tid + i * 256;
        int row = idx >> 3, c = idx & 7;
        cp16(smaddr(smw) + row * 144 + c * 16, A + (long)row * 4096 + c * 8);
        cp16(smaddr(smw + 4608) + row * 144 + c * 16, B + (long)row * 4096 + c * 8);
    }
    cp_commit();
    cp_wait0();
    __syncthreads();

    uint32_t aLd[4], bLd[2];
    {
        int rowl = lane & 15;
        uint32_t kcb = (lane >> 4) * 16;
        #pragma unroll
        for (int mi = 0; mi < 4; mi++)
            aLd[mi] = smaddr(smw) + (m_base + mi * 16 + rowl) * 144 + kcb;
    }
    {
        int rowl = (lane & 7) + ((lane >> 4) * 8);
        uint32_t kcb = ((lane >> 3) & 1) * 16;
        #pragma unroll
        for (int p = 0; p < 2; p++)
            bLd[p] = smaddr(smw + 4608) + (n_base + p * 16 + rowl) * 144 + kcb;
    }

    float acc[4][4][4];
    #pragma unroll
    for (int mi = 0; mi < 4; mi++)
        #pragma unroll
        for (int ni = 0; ni < 4; ni++)
            #pragma unroll
            for (int r = 0; r < 4; r++) acc[mi][ni][r] = 0.f;

    #pragma unroll
    for (int kk = 0; kk < 4; kk++) {
        uint32_t afr[4][4], bfr[2][4];
        #pragma unroll
        for (int mi = 0; mi < 4; mi++) ldsm4(afr[mi], aLd[mi] + kk * 32);
        #pragma unroll
        for (int p = 0; p < 2; p++)    ldsm4(bfr[p], bLd[p] + kk * 32);
        #pragma unroll
        for (int mi = 0; mi < 4; mi++)
            #pragma unroll
            for (int ni = 0; ni < 4; ni++) {
                uint32_t bq[2] = { bfr[ni >> 1][(ni & 1) * 2],
                                   bfr[ni >> 1][(ni & 1) * 2 + 1] };
                mma_f16(acc[mi][ni], afr[mi], bq);
            }
    }

    #pragma unroll
    for (int mi = 0; mi < 4; mi++) {
        int row0 = bm + m_base + mi * 16 + g;
        float2 ml0 = stats[z * Tn + row0];
        float2 ml1 = stats[z * Tn + row0 + 8];
        float i0 = 1.f / ml0.y, i1 = 1.f / ml1.y;
        #pragma unroll
        for (int ni = 0; ni < 4; ni++) {
            int col = bn + n_base + ni * 8 + tg * 2;
            float v0 = __expf(acc[mi][ni][0] - ml0.x) * i0;
            float v1 = __expf(acc[mi][ni][1] - ml0.x) * i0;
            float v2 = __expf(acc[mi][ni][2] - ml1.x) * i1;
            float v3 = __expf(acc[mi][ni][3] - ml1.x) * i1;
            float* Cz = C + (long)z * Tn * Sn;
            *(float2*)&Cz[(long)row0 * Sn + col]       = make_float2(v0, v1);
            *(float2*)&Cz[(long)(row0 + 8) * Sn + col] = make_float2(v2, v3);
        }
    }
}

// ======================= out = LayerNorm(x+res)*g+b ; optional half copy
__global__ __launch_bounds__(256) void add_ln_kernel(
    const float* __restrict__ x, const float* __restrict__ res,
    const float* __restrict__ g, const float* __restrict__ b,
    float* __restrict__ out, __half* __restrict__ out_r)
{
    const long row = (long)blockIdx.x * En;
    const int tid = threadIdx.x;
    float v[4]; float s = 0.f, s2 = 0.f;
    #pragma unroll
    for (int j = 0; j < 4; j++) {
        int i = tid + j * 256;
        float val = x[row + i] + res[row + i];
        v[j] = val; s += val; s2 += val * val;
    }
    __shared__ float sh1[8], sh2[8];
    #pragma unroll
    for (int o = 16; o; o >>= 1) {
        s  += __shfl_xor_sync(0xffffffffu, s, o);
        s2 += __shfl_xor_sync(0xffffffffu, s2, o);
    }
    if ((tid & 31) == 0) { sh1[tid >> 5] = s; sh2[tid >> 5] = s2; }
    __syncthreads();
    float ts = 0.f, ts2 = 0.f;
    #pragma unroll
    for (int w = 0; w < 8; w++) { ts += sh1[w]; ts2 += sh2[w]; }
    const float mu  = ts * (1.f / En);
    const float var = ts2 * (1.f / En) - mu * mu;
    const float inv = rsqrtf(var + 1e-5f);
    #pragma unroll
    for (int j = 0; j < 4; j++) {
        int i = tid + j * 256;
        float o = (v[j] - mu) * inv * g[i] + b[i];
        out[row + i] = o;
        if (out_r) out_r[row + i] = __float2half_rn(o);
    }
}

// ======================= fused fp16 conversion pass =======================
#define NCVT 12
struct CvtJobs {
    const float4* src[NCVT];
    uint2* dst[NCVT];
    int cum[NCVT + 1];
};
__global__ __launch_bounds__(256) void cvt_multi(CvtJobs cj, int total4)
{
    for (int i = blockIdx.x * 256 + threadIdx.x; i < total4; i += gridDim.x * 256) {
        int job = 0;
        #pragma unroll
        for (int t = 0; t < NCVT - 1; t++) if (i >= cj.cum[t + 1]) job = t + 1;
        int off = i - cj.cum[job];
        float4 v = cj.src[job][off];
        __half2 h0 = __floats2half2_rn(v.x, v.y);
        __half2 h1 = __floats2half2_rn(v.z, v.w);
        uint2 u;
        u.x = *(uint32_t*)&h0;
        u.y = *(uint32_t*)&h1;
        cj.dst[job][off] = u;
    }
}

// ======================= host-side =======================
static cudaStream_t s2;
static cudaEvent_t ev0, ev_kv, ev_fe, ev_wg;

static inline void gh_s(JobsH jobs, int M, int N, int K, int njobs, cudaStream_t st)
{
    dim3 grid(N / 256, M / 128, njobs);
    hgemm2<<<grid, 512, H2_SMEM, st>>>(jobs, K, N);
}
static void run_cvt(const float** srcs, __half** dsts, const int* n4s, int njobs,
                    int grid, cudaStream_t st)
{
    CvtJobs cj;
    int c = 0;
    for (int i = 0; i < njobs; i++) {
        cj.src[i] = (const float4*)srcs[i];
        cj.dst[i] = (uint2*)dsts[i];
        cj.cum[i] = c;
        c += n4s[i];
    }
    for (int i = njobs; i <= NCVT; i++) cj.cum[i] = c;
    for (int i = njobs; i < NCVT; i++) { cj.src[i] = nullptr; cj.dst[i] = nullptr; }
    cvt_multi<<<grid, 256, 0, st>>>(cj, c);
}

extern "C" void kernel_launch(void* const* d_in, const int* in_sizes, int n_in,
                              void* d_out, int out_size)
{
    static bool attr_done = false;
    if (!attr_done) {
        cudaFuncSetAttribute((const void*)hgemm2,
                             cudaFuncAttributeMaxDynamicSharedMemorySize, H2_SMEM);
        cudaFuncSetAttribute((const void*)flash_h<true>,
                             cudaFuncAttributeMaxDynamicSharedMemorySize, FLH_SMEM);
        cudaFuncSetAttribute((const void*)flash_h<false>,
                             cudaFuncAttributeMaxDynamicSharedMemorySize, FLH_SMEM);
        cudaFuncSetAttribute((const void*)wgemm,
                             cudaFuncAttributeMaxDynamicSharedMemorySize, WG_SMEM);
        cudaStreamCreateWithFlags(&s2, cudaStreamNonBlocking);
        cudaEventCreateWithFlags(&ev0,   cudaEventDisableTiming);
        cudaEventCreateWithFlags(&ev_kv, cudaEventDisableTiming);
        cudaEventCreateWithFlags(&ev_fe, cudaEventDisableTiming);
        cudaEventCreateWithFlags(&ev_wg, cudaEventDisableTiming);
        attr_done = true;
    }

    const float* state = (const float*)d_in[0];
    const float* enc   = (const float*)d_in[1];
    const float* sa_wq = (const float*)d_in[3];  const float* sa_bq = (const float*)d_in[4];
    const float* sa_wk = (const float*)d_in[5];  const float* sa_bk = (const float*)d_in[6];
    const float* sa_wv = (const float*)d_in[7];  const float* sa_bv = (const float*)d_in[8];
    const float* sa_wo = (const float*)d_in[9];  const float* sa_bo = (const float*)d_in[10];
    const float* ea_wq = (const float*)d_in[11]; const float* ea_bq = (const float*)d_in[12];
    const float* ea_wk = (const float*)d_in[13]; const float* ea_bk = (const float*)d_in[14];
    const float* ea_wv = (const float*)d_in[15]; const float* ea_bv = (const float*)d_in[16];
    const float* ea_wo = (const float*)d_in[17]; const float* ea_bo = (const float*)d_in[18];
    const float* fc1_w = (const float*)d_in[19]; const float* fc1_b = (const float*)d_in[20];
    const float* fc2_w = (const float*)d_in[21]; const float* fc2_b = (const float*)d_in[22];
    const float* ln1_g = (const float*)d_in[23]; const float* ln1_b = (const float*)d_in[24];
    const float* ln2_g = (const float*)d_in[25]; const float* ln2_b = (const float*)d_in[26];
    const float* ln3_g = (const float*)d_in[27]; const float* ln3_b = (const float*)d_in[28];

    float *xq_f, *xk_f, *xv_f, *tmp, *st1, *st2, *rw;
    float *attn_f, *st1r_f, *st2r_f, *ffn_f;
    float2* stats;
    cudaGetSymbolAddress((void**)&xq_f,   g_xq);
    cudaGetSymbolAddress((void**)&xk_f,   g_xk);
    cudaGetSymbolAddress((void**)&xv_f,   g_xv);
    cudaGetSymbolAddress((void**)&attn_f, g_attn);
    cudaGetSymbolAddress((void**)&tmp,    g_tmp);
    cudaGetSymbolAddress((void**)&st1,    g_state1);
    cudaGetSymbolAddress((void**)&st2,    g_state2);
    cudaGetSymbolAddress((void**)&st1r_f, g_st1r);
    cudaGetSymbolAddress((void**)&st2r_f, g_st2r);
    cudaGetSymbolAddress((void**)&ffn_f,  g_ffn);
    cudaGetSymbolAddress((void**)&stats,  g_stats);
    cudaGetSymbolAddress((void**)&rw,     g_rw);

    __half* xq_h   = (__half*)xq_f;
    __half* xk_h   = (__half*)xk_f;
    __half* xv_h   = (__half*)xv_f;
    __half* attn_h = (__half*)attn_f;
    __half* st1r_h = (__half*)st1r_f;
    __half* st2r_h = (__half*)st2r_f;
    __half* ffn_h  = (__half*)ffn_f;
    __half* hp = (__half*)rw;
    __half* h_state = hp + 0L  * MEG;
    __half* h_enc   = hp + 4L  * MEG;
    __half* h_saq   = hp + 8L  * MEG;
    __half* h_sak   = hp + 9L  * MEG;
    __half* h_sav   = hp + 10L * MEG;
    __half* h_sao   = hp + 11L * MEG;
    __half* h_eaq   = hp + 12L * MEG;
    __half* h_eak   = hp + 13L * MEG;
    __half* h_eav   = hp + 14L * MEG;
    __half* h_eao   = hp + 15L * MEG;
    __half* h_fc1   = hp + 16L * MEG;
    __half* h_fc2   = hp + 20L * MEG;
    __half* eak_x   = hp + 24L * MEG;
    __half* eav_x   = hp + 32L * MEG;

    float* out_state = (float*)d_out;
    float* out_attn  = (float*)d_out + (long)Tn * Bn * En;

    // -------- fork point: record on capturing stream, then branch --------
    cudaEventRecord(ev0, 0);
    cudaStreamWaitEvent(s2, ev0, 0);

    // side stream: enc/EA-KV cvt + EA K/V projections (parallel with SA block)
    {
        const float* srcs[3] = {enc, ea_wk, ea_wv};
        __half* dsts[3] = {h_enc, h_eak, h_eav};
        const int n4s[3] = {MEG, MEG/4, MEG/4};
        run_cvt(srcs, dsts, n4s, 3, 512, s2);
    }
    {
        JobsH j = {{{h_enc, h_eak, ea_bk, eak_x, 2},
                    {h_enc, h_eav, ea_bv, eav_x, 2}, {}}};
        gh_s(j, ROWS, En, En, 2, s2);
    }
    cudaEventRecord(ev_kv, s2);

    // main cvt (everything the main chain needs)
    {
        const float* srcs[9] = {state, sa_wq, sa_wk, sa_wv, sa_wo,
                                ea_wq, ea_wo, fc1_w, fc2_w};
        __half* dsts[9] = {h_state, h_saq, h_sak, h_sav, h_sao,
                           h_eaq, h_eao, h_fc1, h_fc2};
        const int n4s[9] = {MEG, MEG/4, MEG/4, MEG/4, MEG/4,
                            MEG/4, MEG/4, MEG, MEG};
        run_cvt(srcs, dsts, n4s, 9, 1024, 0);
    }

    // ---------------- self-attention (fused flash, causal) ----------------
    {
        JobsH j = {{{h_state, h_saq, sa_bq, xq_h, 3},     // Q pre-scaled by 1/8
                    {h_state, h_sak, sa_bk, xk_h, 2},
                    {h_state, h_sav, sa_bv, xv_h, 2}}};
        gh_s(j, ROWS, En, En, 3, 0);
    }
    flash_h<true><<<dim3(Tn / 128, BH), 256, FLH_SMEM>>>(xq_h, xk_h, xv_h, attn_h, nullptr);
    {
        JobsH j = {{{attn_h, h_sao, sa_bo, tmp, 0}, {}, {}}};
        gh_s(j, ROWS, En, En, 1, 0);
    }
    add_ln_kernel<<<ROWS, 256>>>(tmp, state, ln1_g, ln1_b, st1, st1r_h);

    // ---------------- encoder-decoder attention ----------------
    {
        JobsH j = {{{st1r_h, h_eaq, ea_bq, xq_h, 3}, {}, {}}};
        gh_s(j, ROWS, En, En, 1, 0);
    }
    cudaStreamWaitEvent(0, ev_kv, 0);
    flash_h<false><<<dim3(Tn / 128, BH), 256, FLH_SMEM>>>(xq_h, eak_x, eav_x, attn_h, stats);
    cudaEventRecord(ev_fe, 0);

    // side stream: normalized attention weights into d_out, overlapping FFN
    cudaStreamWaitEvent(s2, ev_fe, 0);
    wgemm<<<dim3(Sn / 128, Tn / 128, BH), 256, WG_SMEM, s2>>>(xq_h, eak_x, stats, out_attn);
    cudaEventRecord(ev_wg, s2);

    {
        JobsH j = {{{attn_h, h_eao, ea_bo, tmp, 0}, {}, {}}};
        gh_s(j, ROWS, En, En, 1, 0);
    }
    add_ln_kernel<<<ROWS, 256>>>(tmp, st1, ln2_g, ln2_b, st2, st2r_h);

    // ---------------- FFN ----------------
    {
        JobsH j = {{{st2r_h, h_fc1, fc1_b, ffn_h, 1}, {}, {}}};
        gh_s(j, ROWS, FFn, En, 1, 0);
    }
    {
        JobsH j = {{{ffn_h, h_fc2, fc2_b, tmp, 0}, {}, {}}};
        gh_s(j, ROWS, En, FFn, 1, 0);
    }
    add_ln_kernel<<<ROWS, 256>>>(tmp, st2, ln3_g, ln3_b, out_state, nullptr);

    // join: graph end depends on wgemm
    cudaStreamWaitEvent(0, ev_wg, 0);
}

// round 17
// speedup vs baseline: 1.0609x; 1.0609x over previous
#include <cuda_runtime.h>
#include <cuda_fp16.h>
#include <math.h>
#include <stdint.h>

// Problem dims
#define Tn 1024
#define Sn 1024
#define Bn 4
#define En 1024
#define Hn 16
#define DHn 64
#define FFn 4096
#define ROWS (Tn*Bn)
#define BH (Bn*Hn)
#define MEG (1024*1024)

// -------- scratch (device globals; no allocation) --------
__device__ float g_xq[ROWS*En];        // used as __half
__device__ float g_xk[ROWS*En];        // used as __half
__device__ float g_xv[ROWS*En];        // used as __half
__device__ float g_attn[ROWS*En];      // used as __half
__device__ float g_tmp[ROWS*En];
__device__ float g_state1[ROWS*En];
__device__ float g_state2[ROWS*En];
__device__ float g_st1r[ROWS*En];      // used as __half
__device__ float g_st2r[ROWS*En];      // used as __half
__device__ float g_ffn[ROWS*FFn];      // used as __half
__device__ float2 g_stats[BH*Tn];
__device__ float g_rw[24*MEG];         // used as __half pool (48M halfs)

// ======================= helpers =======================
__device__ __forceinline__ void mma_f16(float* c, const uint32_t* a, const uint32_t* b) {
    asm volatile(
        "mma.sync.aligned.m16n8k16.row.col.f32.f16.f16.f32 "
        "{%0,%1,%2,%3}, {%4,%5,%6,%7}, {%8,%9}, {%0,%1,%2,%3};"
        : "+f"(c[0]), "+f"(c[1]), "+f"(c[2]), "+f"(c[3])
        : "r"(a[0]), "r"(a[1]), "r"(a[2]), "r"(a[3]), "r"(b[0]), "r"(b[1]));
}
__device__ __forceinline__ void ldsm4(uint32_t* r, uint32_t addr) {
    asm volatile("ldmatrix.sync.aligned.m8n8.x4.shared.b16 {%0,%1,%2,%3}, [%4];"
        : "=r"(r[0]), "=r"(r[1]), "=r"(r[2]), "=r"(r[3]) : "r"(addr));
}
__device__ __forceinline__ void ldsm4t(uint32_t* r, uint32_t addr) {
    asm volatile("ldmatrix.sync.aligned.m8n8.x4.trans.shared.b16 {%0,%1,%2,%3}, [%4];"
        : "=r"(r[0]), "=r"(r[1]), "=r"(r[2]), "=r"(r[3]) : "r"(addr));
}
__device__ __forceinline__ void cp16(uint32_t dst, const void* src) {
    asm volatile("cp.async.cg.shared.global [%0], [%1], 16;" :: "r"(dst), "l"(src));
}
__device__ __forceinline__ void cp_commit() {
    asm volatile("cp.async.commit_group;" ::: "memory");
}
__device__ __forceinline__ void cp_wait0() {
    asm volatile("cp.async.wait_group 0;" ::: "memory");
}
__device__ __forceinline__ void cp_wait1() {
    asm volatile("cp.async.wait_group 1;" ::: "memory");
}
__device__ __forceinline__ uint32_t smaddr(const void* p) {
    return (uint32_t)__cvta_generic_to_shared(p);
}
__device__ __forceinline__ uint32_t hex2(uint32_t x) {
    uint32_t r;
    asm("ex2.approx.f16x2 %0, %1;" : "=r"(r) : "r"(x));
    return r;
}
__device__ __forceinline__ uint32_t packh2(float a, float b) {
    __half2 h = __floats2half2_rn(a, b);
    return *(uint32_t*)&h;
}

// ======================= hgemm2: fp16 MMA + ldmatrix, 3-stage, 8 warps ============
// (round-15 proven config: 128x128 tile, 2x4 warp grid, 64x32 warp tiles, 2 CTA/SM)
// postop (per job): 0 fp32 out; 1 relu->half; 2 half; 3 (v*0.125)->half
struct JobH { const __half* A; const __half* B; const float* bias; void* C; int postop; };
struct JobsH { JobH j[3]; };

#define H2_WS 36
#define H2_TILEW (128*H2_WS)
#define H2_SMEM (6*H2_TILEW*4)

__global__ __launch_bounds__(256, 2) void hgemm2(
    JobsH jobs, int K, int N)
{
    extern __shared__ uint32_t smw[];
    const int tid  = threadIdx.x;
    const int lane = tid & 31;
    const int wid  = tid >> 5;
    const int wm = wid & 1, wn = wid >> 1;
    const int m_base = wm * 64, n_base = wn * 32;
    const int g  = lane >> 2;
    const int tg = lane & 3;

    const JobH job = jobs.j[blockIdx.z];
    const int postop = job.postop;
    const int bm = blockIdx.y * 128;
    const int bn = blockIdx.x * 128;
    const __half* A = job.A + (long)bm * K;
    const __half* B = job.B + (long)bn * K;

    const int r0 = tid >> 3, c8 = tid & 7;
    const __half* aPtr = A + (long)r0 * K + c8 * 8;
    const __half* bPtr = B + (long)r0 * K + c8 * 8;
    const uint32_t aSm = smaddr(smw + r0 * H2_WS + c8 * 4);
    const uint32_t bSm = smaddr(smw + H2_TILEW + r0 * H2_WS + c8 * 4);
    const long rowAdv = 32L * K;

    auto load_slab = [&](int s, int st) {
        const uint32_t so = st * (2 * H2_TILEW * 4);
        const __half* ap = aPtr + s * 64;
        const __half* bp = bPtr + s * 64;
        #pragma unroll
        for (int it = 0; it < 4; it++) {
            cp16(aSm + so + it * (32 * H2_WS * 4), ap + it * rowAdv);
            cp16(bSm + so + it * (32 * H2_WS * 4), bp + it * rowAdv);
        }
        cp_commit();
    };

    uint32_t aLd[4];
    {
        int rowl = lane & 15;
        uint32_t kcb = (lane >> 4) * 16;
        #pragma unroll
        for (int mi = 0; mi < 4; mi++)
            aLd[mi] = smaddr(smw + (m_base + mi * 16 + rowl) * H2_WS) + kcb;
    }
    uint32_t bLd[2];
    {
        int rowl = (lane & 7) + ((lane >> 4) * 8);
        uint32_t kcb = ((lane >> 3) & 1) * 16;
        #pragma unroll
        for (int p = 0; p < 2; p++)
            bLd[p] = smaddr(smw + H2_TILEW + (n_base + p * 16 + rowl) * H2_WS) + kcb;
    }

    float acc[4][4][4];
    #pragma unroll
    for (int mi = 0; mi < 4; mi++)
        #pragma unroll
        for (int ni = 0; ni < 4; ni++)
            #pragma unroll
            for (int r = 0; r < 4; r++) acc[mi][ni][r] = 0.f;

    const int nslab = K >> 6;
    load_slab(0, 0);
    if (nslab > 1) load_slab(1, 1); else cp_commit();

    int st = 0;
    for (int s = 0; s < nslab; s++) {
        cp_wait1();
        __syncthreads();
        if (s + 2 < nslab) load_slab(s + 2, (st + 2) % 3);
        else cp_commit();

        const uint32_t so = st * (2 * H2_TILEW * 4);

        #pragma unroll
        for (int kw = 0; kw < 32; kw += 8) {
            uint32_t afr[4][4], bfr[2][4];
            #pragma unroll
            for (int mi = 0; mi < 4; mi++) ldsm4(afr[mi], aLd[mi] + so + kw * 4);
            #pragma unroll
            for (int p = 0; p < 2; p++)    ldsm4(bfr[p], bLd[p] + so + kw * 4);
            #pragma unroll
            for (int mi = 0; mi < 4; mi++)
                #pragma unroll
                for (int ni = 0; ni < 4; ni++) {
                    uint32_t bq[2] = { bfr[ni >> 1][(ni & 1) * 2],
                                       bfr[ni >> 1][(ni & 1) * 2 + 1] };
                    mma_f16(acc[mi][ni], afr[mi], bq);
                }
        }
        st = (st + 1) % 3;
    }

    const float* bias = job.bias;
    #pragma unroll
    for (int mi = 0; mi < 4; mi++) {
        int row0 = bm + m_base + mi * 16 + g;
        #pragma unroll
        for (int ni = 0; ni < 4; ni++) {
            int col = bn + n_base + ni * 8 + tg * 2;
            float b0 = bias[col], b1 = bias[col + 1];
            float v0 = acc[mi][ni][0] + b0;
            float v1 = acc[mi][ni][1] + b1;
            float v2 = acc[mi][ni][2] + b0;
            float v3 = acc[mi][ni][3] + b1;
            if (postop == 0) {
                float* C = (float*)job.C;
                *(float2*)&C[(long)row0 * N + col]       = make_float2(v0, v1);
                *(float2*)&C[(long)(row0 + 8) * N + col] = make_float2(v2, v3);
            } else {
                if (postop == 1) {
                    v0 = fmaxf(v0, 0.f); v1 = fmaxf(v1, 0.f);
                    v2 = fmaxf(v2, 0.f); v3 = fmaxf(v3, 0.f);
                } else if (postop == 3) {
                    v0 *= 0.125f; v1 *= 0.125f; v2 *= 0.125f; v3 *= 0.125f;
                }
                __half* C = (__half*)job.C;
                *(__half2*)&C[(long)row0 * N + col]       = __floats2half2_rn(v0, v1);
                *(__half2*)&C[(long)(row0 + 8) * N + col] = __floats2half2_rn(v2, v3);
            }
        }
    }
}

// ======================= fp16 fused flash attention =======================
// Q pre-scaled by 1/8. exp via ex2.approx.f16x2; row sums via ones-column MMA.
#define FLH_SMEM (18432*4)
#define LOG2E 1.4426950408889634f

template<bool CAUSAL>
__global__ __launch_bounds__(256, 2) void flash_h(
    const __half* __restrict__ Qp, const __half* __restrict__ Kp,
    const __half* __restrict__ Vp, __half* __restrict__ Op,
    float2* __restrict__ stats)
{
    extern __shared__ uint32_t smw[];
    const int tid = threadIdx.x;
    const int lane = tid & 31, w = tid >> 5;
    const int g = lane >> 2, tg = lane & 3;
    const int bh = blockIdx.y;
    const int it = CAUSAL ? ((int)gridDim.x - 1 - (int)blockIdx.x) : (int)blockIdx.x;
    const int t0 = it * 128;
    const int nIter = CAUSAL ? 2 * it + 2 : 16;

    const __half* Qg = Qp + (long)t0 * 4096 + bh * 64;
    const __half* Kg = Kp + bh * 64;
    const __half* Vg = Vp + bh * 64;

    auto loadKV = [&](int j, int buf) {
        const long s0 = (long)j * 64;
        const uint32_t kb = smaddr(smw + 4608 + buf * 2304);
        const uint32_t vb = smaddr(smw + 9216 + buf * 2304);
        #pragma unroll
        for (int i = 0; i < 2; i++) {
            int idx = tid + i * 256;
            int row = idx >> 3, c = idx & 7;
            cp16(kb + row * 144 + c * 16, Kg + (s0 + row) * 4096 + c * 8);
            cp16(vb + row * 144 + c * 16, Vg + (s0 + row) * 4096 + c * 8);
        }
    };

    #pragma unroll
    for (int i = 0; i < 4; i++) {
        int idx = tid + i * 256;
        int row = idx >> 3, c = idx & 7;
        cp16(smaddr(smw) + row * 144 + c * 16, Qg + (long)row * 4096 + c * 8);
    }
    loadKV(0, 0);
    cp_commit();
    cp_wait0();
    __syncthreads();

    uint32_t qf[4][4];
    {
        uint32_t qbase = smaddr(smw) + (16 * w + (lane & 15)) * 144 + (lane >> 4) * 16;
        #pragma unroll
        for (int kk = 0; kk < 4; kk++) ldsm4(qf[kk], qbase + kk * 32);
    }
    uint32_t kbl[4];
    {
        int rowl = (lane & 7) + ((lane >> 4) * 8);
        uint32_t kcb = ((lane >> 3) & 1) * 16;
        #pragma unroll
        for (int p = 0; p < 4; p++)
            kbl[p] = smaddr(smw + 4608) + (p * 16 + rowl) * 144 + kcb;
    }
    uint32_t vbl[4];
    {
        int rowv = (lane & 7) + (((lane >> 3) & 1) * 8);
        uint32_t kcv = (lane >> 4) * 16;
        #pragma unroll
        for (int p = 0; p < 4; p++)
            vbl[p] = smaddr(smw + 9216) + rowv * 144 + kcv + p * 32;
    }
    uint32_t pbase = smaddr(smw + 13824) + (16 * w + (lane & 15)) * 144 + (lane >> 4) * 16;
    __half* Pw = (__half*)(smw + 13824) + (16 * w + g) * 72;

    float acc_o[8][4];
    #pragma unroll
    for (int ni = 0; ni < 8; ni++)
        #pragma unroll
        for (int r = 0; r < 4; r++) acc_o[ni][r] = 0.f;
    float acc_l[4] = {0.f, 0.f, 0.f, 0.f};
    float m0 = -1e30f, m1 = -1e30f;

    const uint32_t ONE2 = 0x3C003C00u;
    uint32_t ones_bq[2] = {ONE2, ONE2};

    for (int j = 0; j < nIter; j++) {
        const int buf = j & 1;
        const uint32_t bofs = buf * 9216;
        if (j + 1 < nIter) { loadKV(j + 1, buf ^ 1); cp_commit(); }

        float s_acc[8][4];
        #pragma unroll
        for (int ni = 0; ni < 8; ni++)
            #pragma unroll
            for (int r = 0; r < 4; r++) s_acc[ni][r] = 0.f;
        #pragma unroll
        for (int kk = 0; kk < 4; kk++) {
            uint32_t kfr[4][4];
            #pragma unroll
            for (int p = 0; p < 4; p++) ldsm4(kfr[p], kbl[p] + bofs + kk * 32);
            #pragma unroll
            for (int ni = 0; ni < 8; ni++) {
                uint32_t bq[2] = { kfr[ni >> 1][(ni & 1) * 2],
                                   kfr[ni >> 1][(ni & 1) * 2 + 1] };
                mma_f16(s_acc[ni], qf[kk], bq);
            }
        }

        const int s0 = j * 64;
        const bool need = CAUSAL && (s0 + 63 > t0 + 16 * w);
        const int tr0 = t0 + 16 * w + g, tr1 = tr0 + 8;
        float mx0 = -1e30f, mx1 = -1e30f;
        #pragma unroll
        for (int ni = 0; ni < 8; ni++) {
            float v0 = s_acc[ni][0];
            float v1 = s_acc[ni][1];
            float v2 = s_acc[ni][2];
            float v3 = s_acc[ni][3];
            if (need) {
                int c0 = s0 + ni * 8 + 2 * tg, c1 = c0 + 1;
                if (c0 > tr0) v0 -= 1e9f;
                if (c1 > tr0) v1 -= 1e9f;
                if (c0 > tr1) v2 -= 1e9f;
                if (c1 > tr1) v3 -= 1e9f;
                s_acc[ni][0] = v0; s_acc[ni][1] = v1;
                s_acc[ni][2] = v2; s_acc[ni][3] = v3;
            }
            mx0 = fmaxf(mx0, fmaxf(v0, v1));
            mx1 = fmaxf(mx1, fmaxf(v2, v3));
        }
        mx0 = fmaxf(mx0, __shfl_xor_sync(0xffffffffu, mx0, 1));
        mx0 = fmaxf(mx0, __shfl_xor_sync(0xffffffffu, mx0, 2));
        mx1 = fmaxf(mx1, __shfl_xor_sync(0xffffffffu, mx1, 1));
        mx1 = fmaxf(mx1, __shfl_xor_sync(0xffffffffu, mx1, 2));
        const float mn0 = fmaxf(m0, mx0), mn1 = fmaxf(m1, mx1);
        const float sc0 = __expf(m0 - mn0), sc1 = __expf(m1 - mn1);
        m0 = mn0; m1 = mn1;
        const float nm0 = m0 * LOG2E, nm1 = m1 * LOG2E;

        #pragma unroll
        for (int ni = 0; ni < 8; ni++) {
            float t0v = fmaf(s_acc[ni][0], LOG2E, -nm0);
            float t1v = fmaf(s_acc[ni][1], LOG2E, -nm0);
            float t2v = fmaf(s_acc[ni][2], LOG2E, -nm1);
            float t3v = fmaf(s_acc[ni][3], LOG2E, -nm1);
            *(uint32_t*)&Pw[ni * 8 + 2 * tg]          = hex2(packh2(t0v, t1v));
            *(uint32_t*)&Pw[8 * 72 + ni * 8 + 2 * tg] = hex2(packh2(t2v, t3v));
        }
        #pragma unroll
        for (int ni = 0; ni < 8; ni++) {
            acc_o[ni][0] *= sc0; acc_o[ni][1] *= sc0;
            acc_o[ni][2] *= sc1; acc_o[ni][3] *= sc1;
        }
        acc_l[0] *= sc0; acc_l[1] *= sc0;
        acc_l[2] *= sc1; acc_l[3] *= sc1;
        __syncwarp();

        #pragma unroll
        for (int kk = 0; kk < 4; kk++) {
            uint32_t pf[4];
            ldsm4(pf, pbase + kk * 32);
            mma_f16(acc_l, pf, ones_bq);
            uint32_t vfr[4][4];
            #pragma unroll
            for (int p = 0; p < 4; p++) ldsm4t(vfr[p], vbl[p] + bofs + kk * 2304);
            #pragma unroll
            for (int ni = 0; ni < 8; ni++) {
                uint32_t bq[2] = { vfr[ni >> 1][(ni & 1) * 2],
                                   vfr[ni >> 1][(ni & 1) * 2 + 1] };
                mma_f16(acc_o[ni], pf, bq);
            }
        }
        if (j + 1 < nIter) cp_wait0();
        __syncthreads();
    }

    const float l0 = acc_l[0], l1 = acc_l[2];
    const float inv0 = 1.f / l0, inv1 = 1.f / l1;
    const int r0 = t0 + 16 * w + g;
    __half* o0 = Op + (long)r0 * 4096 + bh * 64;
    __half* o1 = o0 + 8L * 4096;
    #pragma unroll
    for (int ni = 0; ni < 8; ni++) {
        *(__half2*)&o0[ni * 8 + 2 * tg] =
            __floats2half2_rn(acc_o[ni][0] * inv0, acc_o[ni][1] * inv0);
        *(__half2*)&o1[ni * 8 + 2 * tg] =
            __floats2half2_rn(acc_o[ni][2] * inv1, acc_o[ni][3] * inv1);
    }
    if (!CAUSAL && tg == 0) {
        stats[bh * Tn + r0]     = make_float2(m0, l0);
        stats[bh * Tn + r0 + 8] = make_float2(m1, l1);
    }
}

// ======================= wgemm: EA normalized attention weights ============
#define WG_SMEM (9216*4)

__global__ __launch_bounds__(256, 2) void wgemm(
    const __half* __restrict__ Qh, const __half* __restrict__ Kh,
    const float2* __restrict__ stats, float* __restrict__ C)
{
    extern __shared__ uint32_t smw[];
    const int tid  = threadIdx.x;
    const int lane = tid & 31;
    const int wid  = tid >> 5;
    const int wm = wid & 1, wn = wid >> 1;
    const int m_base = wm * 64, n_base = wn * 32;
    const int g  = lane >> 2;
    const int tg = lane & 3;
    const int z  = blockIdx.z;
    const int bm = blockIdx.y * 128;
    const int bn = blockIdx.x * 128;

    const __half* A = Qh + (long)z * 64 + (long)bm * 4096;
    const __half* B = Kh + (long)z * 64 + (long)bn * 4096;

    #pragma unroll
    for (int i = 0; i < 4; i++) {
        int idx = tid + i * 256;
        int row = idx >> 3, c = idx & 7;
        cp16(smaddr(smw) + row * 144 + c * 16, A + (long)row * 4096 + c * 8);
        cp16(smaddr(smw + 4608) + row * 144 + c * 16, B + (long)row * 4096 + c * 8);
    }
    cp_commit();
    cp_wait0();
    __syncthreads();

    uint32_t aLd[4], bLd[2];
    {
        int rowl = lane & 15;
        uint32_t kcb = (lane >> 4) * 16;
        #pragma unroll
        for (int mi = 0; mi < 4; mi++)
            aLd[mi] = smaddr(smw) + (m_base + mi * 16 + rowl) * 144 + kcb;
    }
    {
        int rowl = (lane & 7) + ((lane >> 4) * 8);
        uint32_t kcb = ((lane >> 3) & 1) * 16;
        #pragma unroll
        for (int p = 0; p < 2; p++)
            bLd[p] = smaddr(smw + 4608) + (n_base + p * 16 + rowl) * 144 + kcb;
    }

    float acc[4][4][4];
    #pragma unroll
    for (int mi = 0; mi < 4; mi++)
        #pragma unroll
        for (int ni = 0; ni < 4; ni++)
            #pragma unroll
            for (int r = 0; r < 4; r++) acc[mi][ni][r] = 0.f;

    #pragma unroll
    for (int kk = 0; kk < 4; kk++) {
        uint32_t afr[4][4], bfr[2][4];
        #pragma unroll
        for (int mi = 0; mi < 4; mi++) ldsm4(afr[mi], aLd[mi] + kk * 32);
        #pragma unroll
        for (int p = 0; p < 2; p++)    ldsm4(bfr[p], bLd[p] + kk * 32);
        #pragma unroll
        for (int mi = 0; mi < 4; mi++)
            #pragma unroll
            for (int ni = 0; ni < 4; ni++) {
                uint32_t bq[2] = { bfr[ni >> 1][(ni & 1) * 2],
                                   bfr[ni >> 1][(ni & 1) * 2 + 1] };
                mma_f16(acc[mi][ni], afr[mi], bq);
            }
    }

    #pragma unroll
    for (int mi = 0; mi < 4; mi++) {
        int row0 = bm + m_base + mi * 16 + g;
        float2 ml0 = stats[z * Tn + row0];
        float2 ml1 = stats[z * Tn + row0 + 8];
        float i0 = 1.f / ml0.y, i1 = 1.f / ml1.y;
        #pragma unroll
        for (int ni = 0; ni < 4; ni++) {
            int col = bn + n_base + ni * 8 + tg * 2;
            float v0 = __expf(acc[mi][ni][0] - ml0.x) * i0;
            float v1 = __expf(acc[mi][ni][1] - ml0.x) * i0;
            float v2 = __expf(acc[mi][ni][2] - ml1.x) * i1;
            float v3 = __expf(acc[mi][ni][3] - ml1.x) * i1;
            float* Cz = C + (long)z * Tn * Sn;
            *(float2*)&Cz[(long)row0 * Sn + col]       = make_float2(v0, v1);
            *(float2*)&Cz[(long)(row0 + 8) * Sn + col] = make_float2(v2, v3);
        }
    }
}

// ======================= out = LayerNorm(x+res)*g+b ; optional half copy
__global__ __launch_bounds__(256) void add_ln_kernel(
    const float* __restrict__ x, const float* __restrict__ res,
    const float* __restrict__ g, const float* __restrict__ b,
    float* __restrict__ out, __half* __restrict__ out_r)
{
    const long row = (long)blockIdx.x * En;
    const int tid = threadIdx.x;
    float v[4]; float s = 0.f, s2 = 0.f;
    #pragma unroll
    for (int j = 0; j < 4; j++) {
        int i = tid + j * 256;
        float val = x[row + i] + res[row + i];
        v[j] = val; s += val; s2 += val * val;
    }
    __shared__ float sh1[8], sh2[8];
    #pragma unroll
    for (int o = 16; o; o >>= 1) {
        s  += __shfl_xor_sync(0xffffffffu, s, o);
        s2 += __shfl_xor_sync(0xffffffffu, s2, o);
    }
    if ((tid & 31) == 0) { sh1[tid >> 5] = s; sh2[tid >> 5] = s2; }
    __syncthreads();
    float ts = 0.f, ts2 = 0.f;
    #pragma unroll
    for (int w = 0; w < 8; w++) { ts += sh1[w]; ts2 += sh2[w]; }
    const float mu  = ts * (1.f / En);
    const float var = ts2 * (1.f / En) - mu * mu;
    const float inv = rsqrtf(var + 1e-5f);
    #pragma unroll
    for (int j = 0; j < 4; j++) {
        int i = tid + j * 256;
        float o = (v[j] - mu) * inv * g[i] + b[i];
        out[row + i] = o;
        if (out_r) out_r[row + i] = __float2half_rn(o);
    }
}

// ======================= fused fp16 conversion pass =======================
#define NCVT 12
struct CvtJobs {
    const float4* src[NCVT];
    uint2* dst[NCVT];
    int cum[NCVT + 1];
};
__global__ __launch_bounds__(256) void cvt_multi(CvtJobs cj, int total4)
{
    for (int i = blockIdx.x * 256 + threadIdx.x; i < total4; i += gridDim.x * 256) {
        int job = 0;
        #pragma unroll
        for (int t = 0; t < NCVT - 1; t++) if (i >= cj.cum[t + 1]) job = t + 1;
        int off = i - cj.cum[job];
        float4 v = cj.src[job][off];
        __half2 h0 = __floats2half2_rn(v.x, v.y);
        __half2 h1 = __floats2half2_rn(v.z, v.w);
        uint2 u;
        u.x = *(uint32_t*)&h0;
        u.y = *(uint32_t*)&h1;
        cj.dst[job][off] = u;
    }
}

// ======================= host-side =======================
static cudaStream_t s2;
static cudaEvent_t ev0, ev_cvtB, ev_kv, ev_fe, ev_wg;

static inline void gh_s(JobsH jobs, int M, int N, int K, int njobs, cudaStream_t st)
{
    dim3 grid(N / 128, M / 128, njobs);
    hgemm2<<<grid, 256, H2_SMEM, st>>>(jobs, K, N);
}
static void run_cvt(const float** srcs, __half** dsts, const int* n4s, int njobs,
                    int grid, cudaStream_t st)
{
    CvtJobs cj;
    int c = 0;
    for (int i = 0; i < njobs; i++) {
        cj.src[i] = (const float4*)srcs[i];
        cj.dst[i] = (uint2*)dsts[i];
        cj.cum[i] = c;
        c += n4s[i];
    }
    for (int i = njobs; i <= NCVT; i++) cj.cum[i] = c;
    for (int i = njobs; i < NCVT; i++) { cj.src[i] = nullptr; cj.dst[i] = nullptr; }
    cvt_multi<<<grid, 256, 0, st>>>(cj, c);
}

extern "C" void kernel_launch(void* const* d_in, const int* in_sizes, int n_in,
                              void* d_out, int out_size)
{
    static bool attr_done = false;
    if (!attr_done) {
        cudaFuncSetAttribute((const void*)hgemm2,
                             cudaFuncAttributeMaxDynamicSharedMemorySize, H2_SMEM);
        cudaFuncSetAttribute((const void*)flash_h<true>,
                             cudaFuncAttributeMaxDynamicSharedMemorySize, FLH_SMEM);
        cudaFuncSetAttribute((const void*)flash_h<false>,
                             cudaFuncAttributeMaxDynamicSharedMemorySize, FLH_SMEM);
        cudaFuncSetAttribute((const void*)wgemm,
                             cudaFuncAttributeMaxDynamicSharedMemorySize, WG_SMEM);
        cudaStreamCreateWithFlags(&s2, cudaStreamNonBlocking);
        cudaEventCreateWithFlags(&ev0,     cudaEventDisableTiming);
        cudaEventCreateWithFlags(&ev_cvtB, cudaEventDisableTiming);
        cudaEventCreateWithFlags(&ev_kv,   cudaEventDisableTiming);
        cudaEventCreateWithFlags(&ev_fe,   cudaEventDisableTiming);
        cudaEventCreateWithFlags(&ev_wg,   cudaEventDisableTiming);
        attr_done = true;
    }

    const float* state = (const float*)d_in[0];
    const float* enc   = (const float*)d_in[1];
    const float* sa_wq = (const float*)d_in[3];  const float* sa_bq = (const float*)d_in[4];
    const float* sa_wk = (const float*)d_in[5];  const float* sa_bk = (const float*)d_in[6];
    const float* sa_wv = (const float*)d_in[7];  const float* sa_bv = (const float*)d_in[8];
    const float* sa_wo = (const float*)d_in[9];  const float* sa_bo = (const float*)d_in[10];
    const float* ea_wq = (const float*)d_in[11]; const float* ea_bq = (const float*)d_in[12];
    const float* ea_wk = (const float*)d_in[13]; const float* ea_bk = (const float*)d_in[14];
    const float* ea_wv = (const float*)d_in[15]; const float* ea_bv = (const float*)d_in[16];
    const float* ea_wo = (const float*)d_in[17]; const float* ea_bo = (const float*)d_in[18];
    const float* fc1_w = (const float*)d_in[19]; const float* fc1_b = (const float*)d_in[20];
    const float* fc2_w = (const float*)d_in[21]; const float* fc2_b = (const float*)d_in[22];
    const float* ln1_g = (const float*)d_in[23]; const float* ln1_b = (const float*)d_in[24];
    const float* ln2_g = (const float*)d_in[25]; const float* ln2_b = (const float*)d_in[26];
    const float* ln3_g = (const float*)d_in[27]; const float* ln3_b = (const float*)d_in[28];

    float *xq_f, *xk_f, *xv_f, *tmp, *st1, *st2, *rw;
    float *attn_f, *st1r_f, *st2r_f, *ffn_f;
    float2* stats;
    cudaGetSymbolAddress((void**)&xq_f,   g_xq);
    cudaGetSymbolAddress((void**)&xk_f,   g_xk);
    cudaGetSymbolAddress((void**)&xv_f,   g_xv);
    cudaGetSymbolAddress((void**)&attn_f, g_attn);
    cudaGetSymbolAddress((void**)&tmp,    g_tmp);
    cudaGetSymbolAddress((void**)&st1,    g_state1);
    cudaGetSymbolAddress((void**)&st2,    g_state2);
    cudaGetSymbolAddress((void**)&st1r_f, g_st1r);
    cudaGetSymbolAddress((void**)&st2r_f, g_st2r);
    cudaGetSymbolAddress((void**)&ffn_f,  g_ffn);
    cudaGetSymbolAddress((void**)&stats,  g_stats);
    cudaGetSymbolAddress((void**)&rw,     g_rw);

    __half* xq_h   = (__half*)xq_f;
    __half* xk_h   = (__half*)xk_f;
    __half* xv_h   = (__half*)xv_f;
    __half* attn_h = (__half*)attn_f;
    __half* st1r_h = (__half*)st1r_f;
    __half* st2r_h = (__half*)st2r_f;
    __half* ffn_h  = (__half*)ffn_f;
    __half* hp = (__half*)rw;
    __half* h_state = hp + 0L  * MEG;
    __half* h_enc   = hp + 4L  * MEG;
    __half* h_saq   = hp + 8L  * MEG;
    __half* h_sak   = hp + 9L  * MEG;
    __half* h_sav   = hp + 10L * MEG;
    __half* h_sao   = hp + 11L * MEG;
    __half* h_eaq   = hp + 12L * MEG;
    __half* h_eak   = hp + 13L * MEG;
    __half* h_eav   = hp + 14L * MEG;
    __half* h_eao   = hp + 15L * MEG;
    __half* h_fc1   = hp + 16L * MEG;
    __half* h_fc2   = hp + 20L * MEG;
    __half* eak_x   = hp + 24L * MEG;
    __half* eav_x   = hp + 32L * MEG;

    float* out_state = (float*)d_out;
    float* out_attn  = (float*)d_out + (long)Tn * Bn * En;

    // -------- fork point: record on capturing stream, then branch --------
    cudaEventRecord(ev0, 0);
    cudaStreamWaitEvent(s2, ev0, 0);

    // side stream: everything NOT needed by the SA block, then EA K/V projections
    {
        const float* srcs[7] = {enc, ea_wk, ea_wv, ea_wq, ea_wo, fc1_w, fc2_w};
        __half* dsts[7] = {h_enc, h_eak, h_eav, h_eaq, h_eao, h_fc1, h_fc2};
        const int n4s[7] = {MEG, MEG/4, MEG/4, MEG/4, MEG/4, MEG, MEG};
        run_cvt(srcs, dsts, n4s, 7, 1024, s2);
    }
    cudaEventRecord(ev_cvtB, s2);
    {
        JobsH j = {{{h_enc, h_eak, ea_bk, eak_x, 2},
                    {h_enc, h_eav, ea_bv, eav_x, 2}, {}}};
        gh_s(j, ROWS, En, En, 2, s2);
    }
    cudaEventRecord(ev_kv, s2);

    // main cvt: only what the SA block needs
    {
        const float* srcs[5] = {state, sa_wq, sa_wk, sa_wv, sa_wo};
        __half* dsts[5] = {h_state, h_saq, h_sak, h_sav, h_sao};
        const int n4s[5] = {MEG, MEG/4, MEG/4, MEG/4, MEG/4};
        run_cvt(srcs, dsts, n4s, 5, 1024, 0);
    }

    // ---------------- self-attention (fused flash, causal) ----------------
    {
        JobsH j = {{{h_state, h_saq, sa_bq, xq_h, 3},     // Q pre-scaled by 1/8
                    {h_state, h_sak, sa_bk, xk_h, 2},
                    {h_state, h_sav, sa_bv, xv_h, 2}}};
        gh_s(j, ROWS, En, En, 3, 0);
    }
    flash_h<true><<<dim3(Tn / 128, BH), 256, FLH_SMEM>>>(xq_h, xk_h, xv_h, attn_h, nullptr);
    {
        JobsH j = {{{attn_h, h_sao, sa_bo, tmp, 0}, {}, {}}};
        gh_s(j, ROWS, En, En, 1, 0);
    }
    add_ln_kernel<<<ROWS, 256>>>(tmp, state, ln1_g, ln1_b, st1, st1r_h);

    // ---------------- encoder-decoder attention ----------------
    cudaStreamWaitEvent(0, ev_cvtB, 0);   // h_eaq ready (also covers h_eao/h_fc1/h_fc2)
    {
        JobsH j = {{{st1r_h, h_eaq, ea_bq, xq_h, 3}, {}, {}}};
        gh_s(j, ROWS, En, En, 1, 0);
    }
    cudaStreamWaitEvent(0, ev_kv, 0);
    flash_h<false><<<dim3(Tn / 128, BH), 256, FLH_SMEM>>>(xq_h, eak_x, eav_x, attn_h, stats);
    cudaEventRecord(ev_fe, 0);

    // side stream: normalized attention weights into d_out, overlapping FFN
    cudaStreamWaitEvent(s2, ev_fe, 0);
    wgemm<<<dim3(Sn / 128, Tn / 128, BH), 256, WG_SMEM, s2>>>(xq_h, eak_x, stats, out_attn);
    cudaEventRecord(ev_wg, s2);

    {
        JobsH j = {{{attn_h, h_eao, ea_bo, tmp, 0}, {}, {}}};
        gh_s(j, ROWS, En, En, 1, 0);
    }
    add_ln_kernel<<<ROWS, 256>>>(tmp, st1, ln2_g, ln2_b, st2, st2r_h);

    // ---------------- FFN ----------------
    {
        JobsH j = {{{st2r_h, h_fc1, fc1_b, ffn_h, 1}, {}, {}}};
        gh_s(j, ROWS, FFn, En, 1, 0);
    }
    {
        JobsH j = {{{ffn_h, h_fc2, fc2_b, tmp, 0}, {}, {}}};
        gh_s(j, ROWS, En, FFn, 1, 0);
    }
    add_ln_kernel<<<ROWS, 256>>>(tmp, st2, ln3_g, ln3_b, out_state, nullptr);

    // join: graph end depends on wgemm
    cudaStreamWaitEvent(0, ev_wg, 0);
}